// round 8
// baseline (speedup 1.0000x reference)
#include <cuda_runtime.h>
#include <math.h>
#include <stdint.h>

#define TT 1024
#define HH 1024
#define EE 8
#define II 1024
#define NP 2048
#define TM 128
#define NIT 32
#define MAX_TILES 24
#define SMEM_SZ 68608   // 17024 floats: 16896 staging/gemm + 128 toks

// ---------------- scratch ----------------
__device__ int   g_counts[EE];
__device__ int   g_offsets[EE];
__device__ int   g_cursor[EE];
__device__ int   g_list[NP];
__device__ int   g_pos[NP];
__device__ float g_w[NP];
__device__ int   g_tile_e[MAX_TILES];
__device__ int   g_tile_row[MAX_TILES];
__device__ int   g_tile_rows[MAX_TILES];
__device__ int   g_ntiles;
__device__ __align__(16) float g_act[(size_t)NP * II];
__device__ __align__(16) float g_down[(size_t)NP * HH];

// ---------------- helpers ----------------
// round fp32 -> nearest-even tf32 so HW truncation is exact & unbiased
__device__ __forceinline__ float rn_tf32(float x){
    uint32_t u = __float_as_uint(x);
    u = (u + 0xFFFu + ((u >> 13) & 1u)) & 0xFFFFE000u;
    return __uint_as_float(u);
}
__device__ __forceinline__ void rn4(float4& v){
    v.x = rn_tf32(v.x); v.y = rn_tf32(v.y); v.z = rn_tf32(v.z); v.w = rn_tf32(v.w);
}
// m16n8k8 tf32 mma (sm_80+ standard PTX; maps to legacy HMMA on sm_103)
__device__ __forceinline__ void mma8(float* c, const float4& a, const float2& b){
    asm volatile(
        "mma.sync.aligned.m16n8k8.row.col.f32.tf32.tf32.f32 "
        "{%0,%1,%2,%3}, {%4,%5,%6,%7}, {%8,%9}, {%0,%1,%2,%3};"
        : "+f"(c[0]), "+f"(c[1]), "+f"(c[2]), "+f"(c[3])
        : "r"(__float_as_uint(a.x)), "r"(__float_as_uint(a.y)),
          "r"(__float_as_uint(a.z)), "r"(__float_as_uint(a.w)),
          "r"(__float_as_uint(b.x)), "r"(__float_as_uint(b.y)));
}
// MUFU-free sigmoid: software exp(-g) + bit-trick reciprocal (3 Newton)
__device__ __forceinline__ float fast_sigmoid(float g){
    float y = -g * 1.4426950408889634f;
    y = fminf(fmaxf(y, -126.f), 126.f);
    float kf = rintf(y);
    float z = (y - kf) * 0.6931471805599453f;
    float p = 1.f + z*(1.f + z*(0.5f + z*(0.16666667f + z*(0.041666668f + z*0.008333334f))));
    float e = p * __int_as_float(((int)kf + 127) << 23);
    float d = 1.f + e;
    float r = __uint_as_float(0x7EF127EAu - __float_as_uint(d));
    r = r*(2.f - d*r); r = r*(2.f - d*r); r = r*(2.f - d*r);
    return r;
}

// ---------------- routing ----------------
__global__ void route_kernel(const float* __restrict__ logits)
{
    int t = threadIdx.x;
    if (t < EE) g_counts[t] = 0;
    __syncthreads();

    float l[EE];
#pragma unroll
    for (int e = 0; e < EE; e++) l[e] = logits[t * EE + e];

    int i0 = 0;
#pragma unroll
    for (int e = 1; e < EE; e++) if (l[e] > l[i0]) i0 = e;
    int i1 = (i0 == 0) ? 1 : 0;
#pragma unroll
    for (int e = 0; e < EE; e++) if (e != i0 && l[e] > l[i1]) i1 = e;

    float e1 = __expf(l[i1] - l[i0]);
    float inv = 1.0f / (1.0f + e1);
    g_w[t * 2 + 0] = inv;
    g_w[t * 2 + 1] = e1 * inv;

    atomicAdd(&g_counts[i0], 1);
    atomicAdd(&g_counts[i1], 1);
    __syncthreads();

    if (t == 0) {
        int off = 0;
        for (int e = 0; e < EE; e++) { g_offsets[e] = off; g_cursor[e] = off; off += g_counts[e]; }
    }
    __syncthreads();

    int p0 = atomicAdd(&g_cursor[i0], 1);
    g_list[p0] = t * 2 + 0; g_pos[t * 2 + 0] = p0;
    int p1 = atomicAdd(&g_cursor[i1], 1);
    g_list[p1] = t * 2 + 1; g_pos[t * 2 + 1] = p1;
    __syncthreads();

    if (t == 0) {
        int n = 0;
        for (int e = 0; e < EE; e++) {
            int c = g_counts[e], o = g_offsets[e];
            for (int s = 0; s < c; s += TM) {
                g_tile_e[n] = e; g_tile_row[n] = o + s; g_tile_rows[n] = min(TM, c - s); n++;
            }
        }
        g_ntiles = n;
    }
}

// Fragment-permuted SMEM layout:
//  A tile 128m x 32k:  frag (fk 0..3, fm 0..7) of 16x8. float off = (fk*8+fm)*128 + lane*4 + reg
//     element (r=m&15, c=k&7): lane=(r&7)*4+(c&3), reg=(r>>3)+2*(c>>2)
//  B tile 128n x 32k:  frag (fk 0..3, fn 0..15) of 8k x 8n. float off = (fk*16+fn)*64 + lane*2 + reg
//     element (k'=k&7, c=n&7): lane=(c)*4+(k'&3)? -> lane=(c&7)*4+(k'&3), reg=k'>>2

// store one prefetched A float4 (m row, k cols c0..c0+3) into permuted buf
__device__ __forceinline__ void stsA(float* dst, int tid, int q, const float4& v){
    int idx = tid + q * 512;
    int m = idx >> 3, c0 = (idx & 7) * 4;
    int fm = m >> 4, r = m & 15, fk = c0 >> 3;
    int reg = (r >> 3) + 2 * ((c0 >> 2) & 1);
    float* base = dst + (fk * 8 + fm) * 128 + (r & 7) * 16 + reg;
    const float* pv = &v.x;
#pragma unroll
    for (int j = 0; j < 4; j++) base[j * 4] = pv[j];
}
// store one prefetched B float4 (k row, n cols c0..c0+3)
__device__ __forceinline__ void stsB(float* dst, int tid, int q, const float4& v){
    int idx = tid + q * 512;
    int k = idx >> 5, c0 = (idx & 31) * 4;
    int fk = k >> 3, kp = k & 7, fn = c0 >> 3;
    int reg = kp >> 2;
    float* base = dst + (fk * 16 + fn) * 64 + ((c0 & 7) * 4 + (kp & 3)) * 2 + reg;
#pragma unroll
    for (int j = 0; j < 4; j++) base[j * 8] = (&v.x)[j];
}

__device__ __forceinline__ void compute_chunk(const float* As, const float* Bs,
                                              int lane, int wm, int wn,
                                              float acc[2][4][4]){
    const float* ab = As + (wm * 2) * 128 + lane * 4;
    const float* bb = Bs + (wn * 4) * 64 + lane * 2;
#pragma unroll
    for (int fk = 0; fk < 4; fk++) {
        float4 a0 = *(const float4*)(ab + fk * 1024);
        float4 a1 = *(const float4*)(ab + fk * 1024 + 128);
#pragma unroll
        for (int j = 0; j < 4; j++) {
            float2 b = *(const float2*)(bb + fk * 1024 + j * 64);
            mma8(acc[0][j], a0, b);
            mma8(acc[1][j], a1, b);
        }
    }
}

// ---------------- gate-up grouped GEMM + fused silu_and_mul ----------------
// grid (MAX_TILES, 16). Block: 128 gathered rows x (64 gate | 64 up) cols.
__global__ __launch_bounds__(512, 1)
void gateup_kernel(const float* __restrict__ hs, const float* __restrict__ W13)
{
    int bx = blockIdx.x;
    if (bx >= g_ntiles) return;
    int e = g_tile_e[bx], row0 = g_tile_row[bx], rows = g_tile_rows[bx];
    int n0 = blockIdx.y * 64;

    extern __shared__ float sm[];
    float* Abuf[2] = { sm, sm + 4096 };
    float* Bbuf[2] = { sm + 8192, sm + 12288 };
    int* toks = (int*)(sm + 16896);

    int tid = threadIdx.x;
    int lane = tid & 31, wid = tid >> 5, wm = wid & 3, wn = wid >> 2;

    if (tid < 128) toks[tid] = (tid < rows) ? (g_list[row0 + tid] >> 1) : -1;
    __syncthreads();

    const float* wb = W13 + (size_t)e * HH * (2 * II);

    // per-thread gmem coords
    int am  = (tid + 0)   >> 3, ac0 = ((tid) & 7) * 4;
    int am1 = (tid + 512) >> 3;                       // ac0 same (idx&7 same)
    int bk  = (tid + 0)   >> 5, bc0 = ((tid) & 31) * 4;
    int bk1 = (tid + 512) >> 5;
    int t0 = toks[am], t1 = toks[am1];
    const float* bcol  = wb + ((bc0 < 64) ? (n0 + bc0) : (II + n0 + (bc0 - 64)));

    float4 pa[2], pb[2];
#define LDGA(it) { int kk = (it)*32; \
    pa[0] = (t0 >= 0) ? *(const float4*)(hs + (size_t)t0 * HH + kk + ac0) : make_float4(0,0,0,0); \
    pa[1] = (t1 >= 0) ? *(const float4*)(hs + (size_t)t1 * HH + kk + ac0) : make_float4(0,0,0,0); \
    rn4(pa[0]); rn4(pa[1]); }
#define LDGB(it) { int kk = (it)*32; \
    pb[0] = *(const float4*)(bcol + (size_t)(kk + bk ) * (2*II)); \
    pb[1] = *(const float4*)(bcol + (size_t)(kk + bk1) * (2*II)); \
    rn4(pb[0]); rn4(pb[1]); }

    float acc[2][4][4] = {};

    LDGA(0); LDGB(0);
    stsA(Abuf[0], tid, 0, pa[0]); stsA(Abuf[0], tid, 1, pa[1]);
    stsB(Bbuf[0], tid, 0, pb[0]); stsB(Bbuf[0], tid, 1, pb[1]);
    LDGA(1); LDGB(1);
    __syncthreads();

    for (int it = 0; it < NIT; it++) {
        int cur = it & 1;
        if (it + 1 < NIT) {
            stsA(Abuf[1 - cur], tid, 0, pa[0]); stsA(Abuf[1 - cur], tid, 1, pa[1]);
            stsB(Bbuf[1 - cur], tid, 0, pb[0]); stsB(Bbuf[1 - cur], tid, 1, pb[1]);
            if (it + 2 < NIT) { LDGA(it + 2); LDGB(it + 2); }
        }
        compute_chunk(Abuf[cur], Bbuf[cur], lane, wm, wn, acc);
        __syncthreads();
    }

    // stage accs -> smem (stride 132), cols 0..63 gate, 64..127 up
    int g = lane >> 2, t = lane & 3;
#pragma unroll
    for (int i = 0; i < 2; i++)
#pragma unroll
        for (int j = 0; j < 4; j++)
#pragma unroll
            for (int r = 0; r < 4; r++) {
                int row = wm * 32 + i * 16 + ((r >> 1) << 3) + g;
                int col = wn * 32 + j * 8 + t * 2 + (r & 1);
                sm[row * 132 + col] = acc[i][j][r];
            }
    __syncthreads();

#pragma unroll
    for (int q = 0; q < 4; q++) {
        int idx = tid + q * 512;
        int row = idx >> 4, c4 = (idx & 15) * 4;
        if (row < rows) {
            float4 gv = *(const float4*)(sm + row * 132 + c4);
            float4 uv = *(const float4*)(sm + row * 132 + 64 + c4);
            float4 o;
            o.x = gv.x * fast_sigmoid(gv.x) * uv.x;
            o.y = gv.y * fast_sigmoid(gv.y) * uv.y;
            o.z = gv.z * fast_sigmoid(gv.z) * uv.z;
            o.w = gv.w * fast_sigmoid(gv.w) * uv.w;
            *(float4*)(g_act + (size_t)(row0 + row) * II + n0 + c4) = o;
        }
    }
#undef LDGA
#undef LDGB
}

// ---------------- down grouped GEMM, pre-weighted --------------------------
// grid (MAX_TILES, 8). Block: 128 act rows x 128 out cols.
__global__ __launch_bounds__(512, 1)
void down_kernel(const float* __restrict__ W2)
{
    int bx = blockIdx.x;
    if (bx >= g_ntiles) return;
    int e = g_tile_e[bx], row0 = g_tile_row[bx], rows = g_tile_rows[bx];
    int n0 = blockIdx.y * 128;

    extern __shared__ float sm[];
    float* Abuf[2] = { sm, sm + 4096 };
    float* Bbuf[2] = { sm + 8192, sm + 12288 };

    int tid = threadIdx.x;
    int lane = tid & 31, wid = tid >> 5, wm = wid & 3, wn = wid >> 2;

    const float* wb = W2 + (size_t)e * II * HH;

    int am  = (tid + 0)   >> 3, ac0 = ((tid) & 7) * 4;
    int am1 = (tid + 512) >> 3;
    int bk  = (tid + 0)   >> 5, bc0 = ((tid) & 31) * 4;
    int bk1 = (tid + 512) >> 5;
    const float* arow0 = (am  < rows) ? (g_act + (size_t)(row0 + am ) * II + ac0) : 0;
    const float* arow1 = (am1 < rows) ? (g_act + (size_t)(row0 + am1) * II + ac0) : 0;
    const float* bcol  = wb + n0 + bc0;

    float4 pa[2], pb[2];
#define LDGA(it) { int kk = (it)*32; \
    pa[0] = arow0 ? *(const float4*)(arow0 + kk) : make_float4(0,0,0,0); \
    pa[1] = arow1 ? *(const float4*)(arow1 + kk) : make_float4(0,0,0,0); \
    rn4(pa[0]); rn4(pa[1]); }
#define LDGB(it) { int kk = (it)*32; \
    pb[0] = *(const float4*)(bcol + (size_t)(kk + bk ) * HH); \
    pb[1] = *(const float4*)(bcol + (size_t)(kk + bk1) * HH); \
    rn4(pb[0]); rn4(pb[1]); }

    float acc[2][4][4] = {};

    LDGA(0); LDGB(0);
    stsA(Abuf[0], tid, 0, pa[0]); stsA(Abuf[0], tid, 1, pa[1]);
    stsB(Bbuf[0], tid, 0, pb[0]); stsB(Bbuf[0], tid, 1, pb[1]);
    LDGA(1); LDGB(1);
    __syncthreads();

    for (int it = 0; it < NIT; it++) {
        int cur = it & 1;
        if (it + 1 < NIT) {
            stsA(Abuf[1 - cur], tid, 0, pa[0]); stsA(Abuf[1 - cur], tid, 1, pa[1]);
            stsB(Bbuf[1 - cur], tid, 0, pb[0]); stsB(Bbuf[1 - cur], tid, 1, pb[1]);
            if (it + 2 < NIT) { LDGA(it + 2); LDGB(it + 2); }
        }
        compute_chunk(Abuf[cur], Bbuf[cur], lane, wm, wn, acc);
        __syncthreads();
    }

    int g = lane >> 2, t = lane & 3;
#pragma unroll
    for (int i = 0; i < 2; i++)
#pragma unroll
        for (int j = 0; j < 4; j++)
#pragma unroll
            for (int r = 0; r < 4; r++) {
                int row = wm * 32 + i * 16 + ((r >> 1) << 3) + g;
                int col = wn * 32 + j * 8 + t * 2 + (r & 1);
                sm[row * 132 + col] = acc[i][j][r];
            }
    __syncthreads();

#pragma unroll
    for (int q = 0; q < 8; q++) {
        int idx = tid + q * 512;
        int row = idx >> 5, c4 = (idx & 31) * 4;
        if (row < rows) {
            float w = g_w[g_list[row0 + row]];
            float4 v = *(const float4*)(sm + row * 132 + c4);
            v.x *= w; v.y *= w; v.z *= w; v.w *= w;
            *(float4*)(g_down + (size_t)(row0 + row) * HH + n0 + c4) = v;
        }
    }
#undef LDGA
#undef LDGB
}

// ---------------- combine ----------------
__global__ void combine_kernel(float* __restrict__ out)
{
    int idx = blockIdx.x * blockDim.x + threadIdx.x;
    int t = idx / (HH / 4);
    int c = idx % (HH / 4);
    int p0 = g_pos[t * 2 + 0];
    int p1 = g_pos[t * 2 + 1];
    float4 a = *(const float4*)&g_down[(size_t)p0 * HH + c * 4];
    float4 b = *(const float4*)&g_down[(size_t)p1 * HH + c * 4];
    float4 o;
    o.x = a.x + b.x; o.y = a.y + b.y; o.z = a.z + b.z; o.w = a.w + b.w;
    *(float4*)(out + (size_t)t * HH + c * 4) = o;
}

// ---------------- launch ----------------
extern "C" void kernel_launch(void* const* d_in, const int* in_sizes, int n_in,
                              void* d_out, int out_size)
{
    const float* hs     = (const float*)d_in[0];
    const float* logits = (const float*)d_in[1];
    const float* W13    = (const float*)d_in[2];
    const float* W2     = (const float*)d_in[3];
    float* out = (float*)d_out;

    cudaFuncSetAttribute(gateup_kernel, cudaFuncAttributeMaxDynamicSharedMemorySize, SMEM_SZ);
    cudaFuncSetAttribute(down_kernel,   cudaFuncAttributeMaxDynamicSharedMemorySize, SMEM_SZ);

    route_kernel<<<1, TT>>>(logits);
    gateup_kernel<<<dim3(MAX_TILES, 16), 512, SMEM_SZ>>>(hs, W13);
    down_kernel<<<dim3(MAX_TILES, 8), 512, SMEM_SZ>>>(W2);
    combine_kernel<<<(TT * HH / 4) / 256, 256>>>(out);
}

// round 11
// speedup vs baseline: 1.3473x; 1.3473x over previous
#include <cuda_runtime.h>
#include <math.h>
#include <stdint.h>

#define TT 1024
#define HH 1024
#define EE 8
#define II 1024
#define NP 2048
#define TM 128
#define NIT 32
#define MAX_TILES 24

// SMEM float layout: A0[128*36] A1 B0[32*136] B1 toks
#define A_LD   36
#define B_LD   136
#define A_FL   (128 * A_LD)          // 4608
#define B_FL   (32 * B_LD)           // 4352
#define OFF_A0 0
#define OFF_A1 A_FL
#define OFF_B0 (2 * A_FL)
#define OFF_B1 (2 * A_FL + B_FL)
#define OFF_TOK (2 * A_FL + 2 * B_FL)    // 17920 floats
#define SMEM_SZ ((OFF_TOK + 128) * 4)    // 72192 bytes (epilogue reuses 128*132 = 16896 fl)

// ---------------- scratch ----------------
__device__ int   g_counts[EE];
__device__ int   g_offsets[EE];
__device__ int   g_cursor[EE];
__device__ int   g_list[NP];
__device__ int   g_pos[NP];
__device__ float g_w[NP];
__device__ int   g_tile_e[MAX_TILES];
__device__ int   g_tile_row[MAX_TILES];
__device__ int   g_tile_rows[MAX_TILES];
__device__ int   g_ntiles;
__device__ __align__(16) float g_act[(size_t)NP * II];
__device__ __align__(16) float g_down[(size_t)NP * HH];

// ---------------- helpers ----------------
__device__ __forceinline__ float rn_tf32(float x){
    uint32_t u = __float_as_uint(x);
    u = (u + 0xFFFu + ((u >> 13) & 1u)) & 0xFFFFE000u;
    return __uint_as_float(u);
}
__device__ __forceinline__ void rn4(float4& v){
    v.x = rn_tf32(v.x); v.y = rn_tf32(v.y); v.z = rn_tf32(v.z); v.w = rn_tf32(v.w);
}
__device__ __forceinline__ void mma8(float* c, const float* a, const float* b){
    asm volatile(
        "mma.sync.aligned.m16n8k8.row.col.f32.tf32.tf32.f32 "
        "{%0,%1,%2,%3}, {%4,%5,%6,%7}, {%8,%9}, {%0,%1,%2,%3};"
        : "+f"(c[0]), "+f"(c[1]), "+f"(c[2]), "+f"(c[3])
        : "r"(__float_as_uint(a[0])), "r"(__float_as_uint(a[1])),
          "r"(__float_as_uint(a[2])), "r"(__float_as_uint(a[3])),
          "r"(__float_as_uint(b[0])), "r"(__float_as_uint(b[1])));
}
__device__ __forceinline__ float fast_sigmoid(float g){
    float y = -g * 1.4426950408889634f;
    y = fminf(fmaxf(y, -126.f), 126.f);
    float kf = rintf(y);
    float z = (y - kf) * 0.6931471805599453f;
    float p = 1.f + z*(1.f + z*(0.5f + z*(0.16666667f + z*(0.041666668f + z*0.008333334f))));
    float e = p * __int_as_float(((int)kf + 127) << 23);
    float d = 1.f + e;
    float r = __uint_as_float(0x7EF127EAu - __float_as_uint(d));
    r = r*(2.f - d*r); r = r*(2.f - d*r); r = r*(2.f - d*r);
    return r;
}

// ---------------- routing ----------------
__global__ void route_kernel(const float* __restrict__ logits)
{
    int t = threadIdx.x;
    if (t < EE) g_counts[t] = 0;
    __syncthreads();

    float l[EE];
#pragma unroll
    for (int e = 0; e < EE; e++) l[e] = logits[t * EE + e];

    int i0 = 0;
#pragma unroll
    for (int e = 1; e < EE; e++) if (l[e] > l[i0]) i0 = e;
    int i1 = (i0 == 0) ? 1 : 0;
#pragma unroll
    for (int e = 0; e < EE; e++) if (e != i0 && l[e] > l[i1]) i1 = e;

    float e1 = __expf(l[i1] - l[i0]);
    float inv = 1.0f / (1.0f + e1);
    g_w[t * 2 + 0] = inv;
    g_w[t * 2 + 1] = e1 * inv;

    atomicAdd(&g_counts[i0], 1);
    atomicAdd(&g_counts[i1], 1);
    __syncthreads();

    if (t == 0) {
        int off = 0;
        for (int e = 0; e < EE; e++) { g_offsets[e] = off; g_cursor[e] = off; off += g_counts[e]; }
    }
    __syncthreads();

    int p0 = atomicAdd(&g_cursor[i0], 1);
    g_list[p0] = t * 2 + 0; g_pos[t * 2 + 0] = p0;
    int p1 = atomicAdd(&g_cursor[i1], 1);
    g_list[p1] = t * 2 + 1; g_pos[t * 2 + 1] = p1;
    __syncthreads();

    if (t == 0) {
        int n = 0;
        for (int e = 0; e < EE; e++) {
            int c = g_counts[e], o = g_offsets[e];
            for (int s = 0; s < c; s += TM) {
                g_tile_e[n] = e; g_tile_row[n] = o + s; g_tile_rows[n] = min(TM, c - s); n++;
            }
        }
        g_ntiles = n;
    }
}

// Conflict-free stores into tiles:
// A m-major [m][A_LD]: float4 direct store (phases cover 32 banks)
__device__ __forceinline__ void stsA(float* A, int tid, int q, const float4& v){
    int idx = tid + q * 512;
    int m = idx >> 3, c0 = (idx & 7) * 4;
    *(float4*)(A + m * A_LD + c0) = v;
}
// B k-major [k][B_LD]: float4 direct store
__device__ __forceinline__ void stsB(float* B, int tid, int q, const float4& v){
    int idx = tid + q * 512;
    int k = idx >> 5, c0 = (idx & 31) * 4;
    *(float4*)(B + k * B_LD + c0) = v;
}

// per-chunk compute: warp tile 32m x 32n, K=32 (4 k-frags)
__device__ __forceinline__ void compute_chunk(const float* __restrict__ As,
                                              const float* __restrict__ Bs,
                                              int aoff, int boff,
                                              float acc[2][4][4]){
#pragma unroll
    for (int fk = 0; fk < 4; fk++) {
        const float* ap = As + aoff + fk * 8;
        float a0[4], a1[4];
        a0[0] = ap[0];            a0[1] = ap[8 * A_LD];
        a0[2] = ap[4];            a0[3] = ap[8 * A_LD + 4];
        const float* ap1 = ap + 16 * A_LD;
        a1[0] = ap1[0];           a1[1] = ap1[8 * A_LD];
        a1[2] = ap1[4];           a1[3] = ap1[8 * A_LD + 4];
        const float* bp = Bs + boff + fk * 8 * B_LD;
#pragma unroll
        for (int fn = 0; fn < 4; fn++) {
            float b[2];
            b[0] = bp[fn * 8];
            b[1] = bp[fn * 8 + 4 * B_LD];
            mma8(acc[0][fn], a0, b);
            mma8(acc[1][fn], a1, b);
        }
    }
}

// ---------------- gate-up grouped GEMM + fused silu_and_mul ----------------
// grid (MAX_TILES, 16). Block: 128 gathered rows x (64 gate | 64 up) cols.
__global__ __launch_bounds__(512, 1)
void gateup_kernel(const float* __restrict__ hs, const float* __restrict__ W13)
{
    int bx = blockIdx.x;
    if (bx >= g_ntiles) return;
    int e = g_tile_e[bx], row0 = g_tile_row[bx], rows = g_tile_rows[bx];
    int n0 = blockIdx.y * 64;

    extern __shared__ float sm[];
    float* Ab[2] = { sm + OFF_A0, sm + OFF_A1 };
    float* Bb[2] = { sm + OFF_B0, sm + OFF_B1 };
    int* toks = (int*)(sm + OFF_TOK);

    int tid = threadIdx.x;
    int lane = tid & 31, wid = tid >> 5, wm = wid & 3, wn = wid >> 2;
    int aoff = (wm * 32 + (lane >> 2)) * A_LD + (lane & 3);
    int boff = (lane & 3) * B_LD + wn * 32 + (lane >> 2);

    if (tid < 128) toks[tid] = (tid < rows) ? (g_list[row0 + tid] >> 1) : -1;
    __syncthreads();

    const float* wb = W13 + (size_t)e * HH * (2 * II);

    int am  = (tid + 0)   >> 3, ac0 = ((tid) & 7) * 4;
    int am1 = (tid + 512) >> 3;
    int bk  = (tid + 0)   >> 5, bc0 = ((tid) & 31) * 4;
    int bk1 = (tid + 512) >> 5;
    int t0 = toks[am], t1 = toks[am1];
    const float* bcol = wb + ((bc0 < 64) ? (n0 + bc0) : (II + n0 + (bc0 - 64)));

    float4 pa[2], pb[2];
#define LDGA(it) { int kk = (it)*32; \
    pa[0] = (t0 >= 0) ? *(const float4*)(hs + (size_t)t0 * HH + kk + ac0) : make_float4(0,0,0,0); \
    pa[1] = (t1 >= 0) ? *(const float4*)(hs + (size_t)t1 * HH + kk + ac0) : make_float4(0,0,0,0); \
    rn4(pa[0]); rn4(pa[1]); }
#define LDGB(it) { int kk = (it)*32; \
    pb[0] = *(const float4*)(bcol + (size_t)(kk + bk ) * (2*II)); \
    pb[1] = *(const float4*)(bcol + (size_t)(kk + bk1) * (2*II)); \
    rn4(pb[0]); rn4(pb[1]); }

    float acc[2][4][4] = {};

    LDGA(0); LDGB(0);
    stsA(Ab[0], tid, 0, pa[0]); stsA(Ab[0], tid, 1, pa[1]);
    stsB(Bb[0], tid, 0, pb[0]); stsB(Bb[0], tid, 1, pb[1]);
    LDGA(1); LDGB(1);
    __syncthreads();

    for (int it = 0; it < NIT; it++) {
        int cur = it & 1;
        if (it + 1 < NIT) {
            stsA(Ab[1 - cur], tid, 0, pa[0]); stsA(Ab[1 - cur], tid, 1, pa[1]);
            stsB(Bb[1 - cur], tid, 0, pb[0]); stsB(Bb[1 - cur], tid, 1, pb[1]);
            if (it + 2 < NIT) { LDGA(it + 2); LDGB(it + 2); }
        }
        compute_chunk(Ab[cur], Bb[cur], aoff, boff, acc);
        __syncthreads();
    }

    // stage accs -> smem [128][132], cols 0..63 gate, 64..127 up
    int g = lane >> 2, t = lane & 3;
#pragma unroll
    for (int i = 0; i < 2; i++)
#pragma unroll
        for (int j = 0; j < 4; j++)
#pragma unroll
            for (int r = 0; r < 4; r++) {
                int row = wm * 32 + i * 16 + ((r >> 1) << 3) + g;
                int col = wn * 32 + j * 8 + t * 2 + (r & 1);
                sm[row * 132 + col] = acc[i][j][r];
            }
    __syncthreads();

#pragma unroll
    for (int q = 0; q < 4; q++) {
        int idx = tid + q * 512;
        int row = idx >> 4, c4 = (idx & 15) * 4;
        if (row < rows) {
            float4 gv = *(const float4*)(sm + row * 132 + c4);
            float4 uv = *(const float4*)(sm + row * 132 + 64 + c4);
            float4 o;
            o.x = gv.x * fast_sigmoid(gv.x) * uv.x;
            o.y = gv.y * fast_sigmoid(gv.y) * uv.y;
            o.z = gv.z * fast_sigmoid(gv.z) * uv.z;
            o.w = gv.w * fast_sigmoid(gv.w) * uv.w;
            *(float4*)(g_act + (size_t)(row0 + row) * II + n0 + c4) = o;
        }
    }
#undef LDGA
#undef LDGB
}

// ---------------- down grouped GEMM, pre-weighted --------------------------
// grid (MAX_TILES, 8). Block: 128 act rows x 128 out cols.
__global__ __launch_bounds__(512, 1)
void down_kernel(const float* __restrict__ W2)
{
    int bx = blockIdx.x;
    if (bx >= g_ntiles) return;
    int e = g_tile_e[bx], row0 = g_tile_row[bx], rows = g_tile_rows[bx];
    int n0 = blockIdx.y * 128;

    extern __shared__ float sm[];
    float* Ab[2] = { sm + OFF_A0, sm + OFF_A1 };
    float* Bb[2] = { sm + OFF_B0, sm + OFF_B1 };

    int tid = threadIdx.x;
    int lane = tid & 31, wid = tid >> 5, wm = wid & 3, wn = wid >> 2;
    int aoff = (wm * 32 + (lane >> 2)) * A_LD + (lane & 3);
    int boff = (lane & 3) * B_LD + wn * 32 + (lane >> 2);

    const float* wb = W2 + (size_t)e * II * HH;

    int am  = (tid + 0)   >> 3, ac0 = ((tid) & 7) * 4;
    int am1 = (tid + 512) >> 3;
    int bk  = (tid + 0)   >> 5, bc0 = ((tid) & 31) * 4;
    int bk1 = (tid + 512) >> 5;
    const float* arow0 = (am  < rows) ? (g_act + (size_t)(row0 + am ) * II + ac0) : 0;
    const float* arow1 = (am1 < rows) ? (g_act + (size_t)(row0 + am1) * II + ac0) : 0;
    const float* bcol  = wb + n0 + bc0;

    float4 pa[2], pb[2];
#define LDGA(it) { int kk = (it)*32; \
    pa[0] = arow0 ? *(const float4*)(arow0 + kk) : make_float4(0,0,0,0); \
    pa[1] = arow1 ? *(const float4*)(arow1 + kk) : make_float4(0,0,0,0); \
    rn4(pa[0]); rn4(pa[1]); }
#define LDGB(it) { int kk = (it)*32; \
    pb[0] = *(const float4*)(bcol + (size_t)(kk + bk ) * HH); \
    pb[1] = *(const float4*)(bcol + (size_t)(kk + bk1) * HH); \
    rn4(pb[0]); rn4(pb[1]); }

    float acc[2][4][4] = {};

    LDGA(0); LDGB(0);
    stsA(Ab[0], tid, 0, pa[0]); stsA(Ab[0], tid, 1, pa[1]);
    stsB(Bb[0], tid, 0, pb[0]); stsB(Bb[0], tid, 1, pb[1]);
    LDGA(1); LDGB(1);
    __syncthreads();

    for (int it = 0; it < NIT; it++) {
        int cur = it & 1;
        if (it + 1 < NIT) {
            stsA(Ab[1 - cur], tid, 0, pa[0]); stsA(Ab[1 - cur], tid, 1, pa[1]);
            stsB(Bb[1 - cur], tid, 0, pb[0]); stsB(Bb[1 - cur], tid, 1, pb[1]);
            if (it + 2 < NIT) { LDGA(it + 2); LDGB(it + 2); }
        }
        compute_chunk(Ab[cur], Bb[cur], aoff, boff, acc);
        __syncthreads();
    }

    int g = lane >> 2, t = lane & 3;
#pragma unroll
    for (int i = 0; i < 2; i++)
#pragma unroll
        for (int j = 0; j < 4; j++)
#pragma unroll
            for (int r = 0; r < 4; r++) {
                int row = wm * 32 + i * 16 + ((r >> 1) << 3) + g;
                int col = wn * 32 + j * 8 + t * 2 + (r & 1);
                sm[row * 132 + col] = acc[i][j][r];
            }
    __syncthreads();

#pragma unroll
    for (int q = 0; q < 8; q++) {
        int idx = tid + q * 512;
        int row = idx >> 5, c4 = (idx & 31) * 4;
        if (row < rows) {
            float w = g_w[g_list[row0 + row]];
            float4 v = *(const float4*)(sm + row * 132 + c4);
            v.x *= w; v.y *= w; v.z *= w; v.w *= w;
            *(float4*)(g_down + (size_t)(row0 + row) * HH + n0 + c4) = v;
        }
    }
#undef LDGA
#undef LDGB
}

// ---------------- combine ----------------
__global__ void combine_kernel(float* __restrict__ out)
{
    int idx = blockIdx.x * blockDim.x + threadIdx.x;
    int t = idx / (HH / 4);
    int c = idx % (HH / 4);
    int p0 = g_pos[t * 2 + 0];
    int p1 = g_pos[t * 2 + 1];
    float4 a = *(const float4*)&g_down[(size_t)p0 * HH + c * 4];
    float4 b = *(const float4*)&g_down[(size_t)p1 * HH + c * 4];
    float4 o;
    o.x = a.x + b.x; o.y = a.y + b.y; o.z = a.z + b.z; o.w = a.w + b.w;
    *(float4*)(out + (size_t)t * HH + c * 4) = o;
}

// ---------------- launch ----------------
extern "C" void kernel_launch(void* const* d_in, const int* in_sizes, int n_in,
                              void* d_out, int out_size)
{
    const float* hs     = (const float*)d_in[0];
    const float* logits = (const float*)d_in[1];
    const float* W13    = (const float*)d_in[2];
    const float* W2     = (const float*)d_in[3];
    float* out = (float*)d_out;

    cudaFuncSetAttribute(gateup_kernel, cudaFuncAttributeMaxDynamicSharedMemorySize, SMEM_SZ);
    cudaFuncSetAttribute(down_kernel,   cudaFuncAttributeMaxDynamicSharedMemorySize, SMEM_SZ);

    route_kernel<<<1, TT>>>(logits);
    gateup_kernel<<<dim3(MAX_TILES, 16), 512, SMEM_SZ>>>(hs, W13);
    down_kernel<<<dim3(MAX_TILES, 8), 512, SMEM_SZ>>>(W2);
    combine_kernel<<<(TT * HH / 4) / 256, 256>>>(out);
}

// round 15
// speedup vs baseline: 1.4402x; 1.0690x over previous
#include <cuda_runtime.h>
#include <math.h>
#include <stdint.h>

#define TT 1024
#define HH 1024
#define EE 8
#define II 1024
#define NP 2048
#define TM 128
#define NIT 32
#define MAX_TILES 24
#define NSM 148

// SMEM float layout: A0[128*36] A1 B0[32*136] B1 tok/w
#define A_LD   36
#define B_LD   136
#define A_FL   (128 * A_LD)
#define B_FL   (32 * B_LD)
#define OFF_A0 0
#define OFF_A1 A_FL
#define OFF_B0 (2 * A_FL)
#define OFF_B1 (2 * A_FL + B_FL)
#define OFF_TOK (2 * A_FL + 2 * B_FL)        // 17920 floats
#define SMEM_SZ ((OFF_TOK + 256 + 8) * 4)    // toks[128] + ws[128] + item

// ---------------- scratch ----------------
__device__ int   g_counts[EE];
__device__ int   g_offsets[EE];
__device__ int   g_cursor[EE];
__device__ int   g_list[NP];
__device__ float g_w[NP];
__device__ int   g_tile_e[MAX_TILES];
__device__ int   g_tile_row[MAX_TILES];
__device__ int   g_tile_rows[MAX_TILES];
__device__ int   g_ntiles;
__device__ int   g_item;
__device__ int   g_done[MAX_TILES];
__device__ __align__(16) float g_act[(size_t)NP * II];

// ---------------- helpers ----------------
__device__ __forceinline__ float rn_tf32(float x){
    uint32_t u = __float_as_uint(x);
    u = (u + 0xFFFu + ((u >> 13) & 1u)) & 0xFFFFE000u;
    return __uint_as_float(u);
}
__device__ __forceinline__ void rn4(float4& v){
    v.x = rn_tf32(v.x); v.y = rn_tf32(v.y); v.z = rn_tf32(v.z); v.w = rn_tf32(v.w);
}
__device__ __forceinline__ void mma8(float* c, const float* a, const float* b){
    asm volatile(
        "mma.sync.aligned.m16n8k8.row.col.f32.tf32.tf32.f32 "
        "{%0,%1,%2,%3}, {%4,%5,%6,%7}, {%8,%9}, {%0,%1,%2,%3};"
        : "+f"(c[0]), "+f"(c[1]), "+f"(c[2]), "+f"(c[3])
        : "r"(__float_as_uint(a[0])), "r"(__float_as_uint(a[1])),
          "r"(__float_as_uint(a[2])), "r"(__float_as_uint(a[3])),
          "r"(__float_as_uint(b[0])), "r"(__float_as_uint(b[1])));
}
__device__ __forceinline__ float fast_sigmoid(float g){
    float y = -g * 1.4426950408889634f;
    y = fminf(fmaxf(y, -126.f), 126.f);
    float kf = rintf(y);
    float z = (y - kf) * 0.6931471805599453f;
    float p = 1.f + z*(1.f + z*(0.5f + z*(0.16666667f + z*(0.041666668f + z*0.008333334f))));
    float e = p * __int_as_float(((int)kf + 127) << 23);
    float d = 1.f + e;
    float r = __uint_as_float(0x7EF127EAu - __float_as_uint(d));
    r = r*(2.f - d*r); r = r*(2.f - d*r); r = r*(2.f - d*r);
    return r;
}

// ---------------- routing ----------------
__global__ void route_kernel(const float* __restrict__ logits)
{
    int t = threadIdx.x;
    if (t < EE) g_counts[t] = 0;
    if (t < MAX_TILES) g_done[t] = 0;
    if (t == 0) g_item = 0;
    __syncthreads();

    float l[EE];
#pragma unroll
    for (int e = 0; e < EE; e++) l[e] = logits[t * EE + e];

    int i0 = 0;
#pragma unroll
    for (int e = 1; e < EE; e++) if (l[e] > l[i0]) i0 = e;
    int i1 = (i0 == 0) ? 1 : 0;
#pragma unroll
    for (int e = 0; e < EE; e++) if (e != i0 && l[e] > l[i1]) i1 = e;

    float e1 = __expf(l[i1] - l[i0]);
    float inv = 1.0f / (1.0f + e1);
    g_w[t * 2 + 0] = inv;
    g_w[t * 2 + 1] = e1 * inv;

    atomicAdd(&g_counts[i0], 1);
    atomicAdd(&g_counts[i1], 1);
    __syncthreads();

    if (t == 0) {
        int off = 0;
        for (int e = 0; e < EE; e++) { g_offsets[e] = off; g_cursor[e] = off; off += g_counts[e]; }
    }
    __syncthreads();

    int p0 = atomicAdd(&g_cursor[i0], 1);
    g_list[p0] = t * 2 + 0;
    int p1 = atomicAdd(&g_cursor[i1], 1);
    g_list[p1] = t * 2 + 1;
    __syncthreads();

    if (t == 0) {
        int n = 0;
        for (int e = 0; e < EE; e++) {
            int c = g_counts[e], o = g_offsets[e];
            for (int s = 0; s < c; s += TM) {
                g_tile_e[n] = e; g_tile_row[n] = o + s; g_tile_rows[n] = min(TM, c - s); n++;
            }
        }
        g_ntiles = n;
    }
}

__global__ void zero_kernel(float* __restrict__ out)
{
    int idx = blockIdx.x * blockDim.x + threadIdx.x;
    ((float4*)out)[idx] = make_float4(0.f, 0.f, 0.f, 0.f);
}

// conflict-free tile stores
__device__ __forceinline__ void stsA(float* A, int tid, int q, const float4& v){
    int idx = tid + q * 512;
    int m = idx >> 3, c0 = (idx & 7) * 4;
    *(float4*)(A + m * A_LD + c0) = v;
}
__device__ __forceinline__ void stsB(float* B, int tid, int q, const float4& v){
    int idx = tid + q * 512;
    int k = idx >> 5, c0 = (idx & 31) * 4;
    *(float4*)(B + k * B_LD + c0) = v;
}

// warp tile 32m x 32n, K=32
__device__ __forceinline__ void compute_chunk(const float* __restrict__ As,
                                              const float* __restrict__ Bs,
                                              int aoff, int boff,
                                              float acc[2][4][4]){
#pragma unroll
    for (int fk = 0; fk < 4; fk++) {
        const float* ap = As + aoff + fk * 8;
        float a0[4], a1[4];
        a0[0] = ap[0]; a0[1] = ap[8 * A_LD]; a0[2] = ap[4]; a0[3] = ap[8 * A_LD + 4];
        const float* ap1 = ap + 16 * A_LD;
        a1[0] = ap1[0]; a1[1] = ap1[8 * A_LD]; a1[2] = ap1[4]; a1[3] = ap1[8 * A_LD + 4];
        const float* bp = Bs + boff + fk * 8 * B_LD;
#pragma unroll
        for (int fn = 0; fn < 4; fn++) {
            float b[2];
            b[0] = bp[fn * 8];
            b[1] = bp[fn * 8 + 4 * B_LD];
            mma8(acc[0][fn], a0, b);
            mma8(acc[1][fn], a1, b);
        }
    }
}
// warp tile 32m x 16n (down), K=32
__device__ __forceinline__ void compute_chunk_dn(const float* __restrict__ As,
                                                 const float* __restrict__ Bs,
                                                 int aoff, int boff,
                                                 float acc[2][2][4]){
#pragma unroll
    for (int fk = 0; fk < 4; fk++) {
        const float* ap = As + aoff + fk * 8;
        float a0[4], a1[4];
        a0[0] = ap[0]; a0[1] = ap[8 * A_LD]; a0[2] = ap[4]; a0[3] = ap[8 * A_LD + 4];
        const float* ap1 = ap + 16 * A_LD;
        a1[0] = ap1[0]; a1[1] = ap1[8 * A_LD]; a1[2] = ap1[4]; a1[3] = ap1[8 * A_LD + 4];
        const float* bp = Bs + boff + fk * 8 * B_LD;
#pragma unroll
        for (int fn = 0; fn < 2; fn++) {
            float b[2];
            b[0] = bp[fn * 8];
            b[1] = bp[fn * 8 + 4 * B_LD];
            mma8(acc[0][fn], a0, b);
            mma8(acc[1][fn], a1, b);
        }
    }
}

// ---------------- gate-up item: 128 rows x (64 gate | 64 up) ---------------
__device__ void do_gateup(float* sm, const float* __restrict__ hs,
                          const float* __restrict__ W13,
                          int tileid, int colblk)
{
    int e = g_tile_e[tileid], row0 = g_tile_row[tileid], rows = g_tile_rows[tileid];
    int n0 = colblk * 64;

    float* Ab[2] = { sm + OFF_A0, sm + OFF_A1 };
    float* Bb[2] = { sm + OFF_B0, sm + OFF_B1 };
    int* toks = (int*)(sm + OFF_TOK);

    int tid = threadIdx.x;
    int lane = tid & 31, wid = tid >> 5, wm = wid & 3, wn = wid >> 2;
    int aoff = (wm * 32 + (lane >> 2)) * A_LD + (lane & 3);
    int boff = (lane & 3) * B_LD + wn * 32 + (lane >> 2);

    if (tid < 128) toks[tid] = (tid < rows) ? (g_list[row0 + tid] >> 1) : -1;
    __syncthreads();

    const float* wb = W13 + (size_t)e * HH * (2 * II);

    int am  = (tid + 0)   >> 3, ac0 = (tid & 7) * 4;
    int am1 = (tid + 512) >> 3;
    int bk  = (tid + 0)   >> 5, bc0 = (tid & 31) * 4;
    int bk1 = (tid + 512) >> 5;
    int t0 = toks[am], t1 = toks[am1];
    const float* bcol = wb + ((bc0 < 64) ? (n0 + bc0) : (II + n0 + (bc0 - 64)));

    float4 pa[2], pb[2];
#define LDGA(it) { int kk = (it)*32; \
    pa[0] = (t0 >= 0) ? *(const float4*)(hs + (size_t)t0 * HH + kk + ac0) : make_float4(0,0,0,0); \
    pa[1] = (t1 >= 0) ? *(const float4*)(hs + (size_t)t1 * HH + kk + ac0) : make_float4(0,0,0,0); \
    rn4(pa[0]); rn4(pa[1]); }
#define LDGB(it) { int kk = (it)*32; \
    pb[0] = *(const float4*)(bcol + (size_t)(kk + bk ) * (2*II)); \
    pb[1] = *(const float4*)(bcol + (size_t)(kk + bk1) * (2*II)); \
    rn4(pb[0]); rn4(pb[1]); }

    float acc[2][4][4] = {};

    LDGA(0); LDGB(0);
    stsA(Ab[0], tid, 0, pa[0]); stsA(Ab[0], tid, 1, pa[1]);
    stsB(Bb[0], tid, 0, pb[0]); stsB(Bb[0], tid, 1, pb[1]);
    LDGA(1); LDGB(1);
    __syncthreads();

    for (int it = 0; it < NIT; it++) {
        int cur = it & 1;
        if (it + 1 < NIT) {
            stsA(Ab[1 - cur], tid, 0, pa[0]); stsA(Ab[1 - cur], tid, 1, pa[1]);
            stsB(Bb[1 - cur], tid, 0, pb[0]); stsB(Bb[1 - cur], tid, 1, pb[1]);
            if (it + 2 < NIT) { LDGA(it + 2); LDGB(it + 2); }
        }
        compute_chunk(Ab[cur], Bb[cur], aoff, boff, acc);
        __syncthreads();
    }
#undef LDGA
#undef LDGB

    // stage accs -> smem [128][132], cols 0..63 gate, 64..127 up
    int g = lane >> 2, t = lane & 3;
#pragma unroll
    for (int i = 0; i < 2; i++)
#pragma unroll
        for (int j = 0; j < 4; j++)
#pragma unroll
            for (int r = 0; r < 4; r++) {
                int row = wm * 32 + i * 16 + ((r >> 1) << 3) + g;
                int col = wn * 32 + j * 8 + t * 2 + (r & 1);
                sm[row * 132 + col] = acc[i][j][r];
            }
    __syncthreads();

#pragma unroll
    for (int q = 0; q < 4; q++) {
        int idx = tid + q * 512;
        int row = idx >> 4, c4 = (idx & 15) * 4;
        if (row < rows) {
            float4 gv = *(const float4*)(sm + row * 132 + c4);
            float4 uv = *(const float4*)(sm + row * 132 + 64 + c4);
            float4 o;
            o.x = gv.x * fast_sigmoid(gv.x) * uv.x;
            o.y = gv.y * fast_sigmoid(gv.y) * uv.y;
            o.z = gv.z * fast_sigmoid(gv.z) * uv.z;
            o.w = gv.w * fast_sigmoid(gv.w) * uv.w;
            *(float4*)(g_act + (size_t)(row0 + row) * II + n0 + c4) = o;
        }
    }
    __threadfence();
    __syncthreads();
    if (tid == 0) atomicAdd(&g_done[tileid], 1);
}

// ---------------- down item: 128 rows x 64 cols, atomicAdd into out --------
__device__ void do_down(float* sm, const float* __restrict__ W2,
                        float* __restrict__ out, int tileid, int colblk)
{
    int e = g_tile_e[tileid], row0 = g_tile_row[tileid], rows = g_tile_rows[tileid];
    int n0 = colblk * 64;
    int tid = threadIdx.x;

    // wait for all 16 gateup col-blocks of this row-tile
    if (tid == 0) { while (atomicAdd(&g_done[tileid], 0) < 16) { } }
    __syncthreads();
    __threadfence();

    float* Ab[2] = { sm + OFF_A0, sm + OFF_A1 };
    float* Bb[2] = { sm + OFF_B0, sm + OFF_B1 };
    int*   toks  = (int*)(sm + OFF_TOK);
    float* ws    = sm + OFF_TOK + 128;

    int lane = tid & 31, wid = tid >> 5, wm = wid & 3, wn = wid >> 2;
    int aoff = (wm * 32 + (lane >> 2)) * A_LD + (lane & 3);
    int boff = (lane & 3) * B_LD + wn * 16 + (lane >> 2);

    if (tid < 128) {
        if (tid < rows) {
            int li = g_list[row0 + tid];
            toks[tid] = li >> 1;
            ws[tid] = g_w[li];
        } else { toks[tid] = -1; ws[tid] = 0.f; }
    }
    __syncthreads();

    const float* wb = W2 + (size_t)e * II * HH;

    int am  = (tid + 0)   >> 3, ac0 = (tid & 7) * 4;
    int am1 = (tid + 512) >> 3;
    int bk  = tid >> 4, bc0 = (tid & 15) * 4;
    const float* arow0 = (am  < rows) ? (g_act + (size_t)(row0 + am ) * II + ac0) : 0;
    const float* arow1 = (am1 < rows) ? (g_act + (size_t)(row0 + am1) * II + ac0) : 0;
    const float* bcol  = wb + n0 + bc0;

    float4 pa[2], pb;
#define LDGA(it) { int kk = (it)*32; \
    pa[0] = arow0 ? *(const float4*)(arow0 + kk) : make_float4(0,0,0,0); \
    pa[1] = arow1 ? *(const float4*)(arow1 + kk) : make_float4(0,0,0,0); \
    rn4(pa[0]); rn4(pa[1]); }
#define LDGB(it) { int kk = (it)*32; \
    pb = *(const float4*)(bcol + (size_t)(kk + bk) * HH); \
    rn4(pb); }

    float acc[2][2][4] = {};

    LDGA(0); LDGB(0);
    stsA(Ab[0], tid, 0, pa[0]); stsA(Ab[0], tid, 1, pa[1]);
    { int k = tid >> 4, c0 = (tid & 15) * 4; *(float4*)(Bb[0] + k * B_LD + c0) = pb; }
    LDGA(1); LDGB(1);
    __syncthreads();

    for (int it = 0; it < NIT; it++) {
        int cur = it & 1;
        if (it + 1 < NIT) {
            stsA(Ab[1 - cur], tid, 0, pa[0]); stsA(Ab[1 - cur], tid, 1, pa[1]);
            { int k = tid >> 4, c0 = (tid & 15) * 4; *(float4*)(Bb[1 - cur] + k * B_LD + c0) = pb; }
            if (it + 2 < NIT) { LDGA(it + 2); LDGB(it + 2); }
        }
        compute_chunk_dn(Ab[cur], Bb[cur], aoff, boff, acc);
        __syncthreads();
    }
#undef LDGA
#undef LDGB

    // direct atomic combine: out[token] += w * acc (2 commutative adds/elem)
    int gq = lane >> 2, tq = lane & 3;
#pragma unroll
    for (int i = 0; i < 2; i++)
#pragma unroll
        for (int rh = 0; rh < 2; rh++) {
            int row = wm * 32 + i * 16 + rh * 8 + gq;
            if (row < rows) {
                int tok = toks[row];
                float w = ws[row];
                float* ob = out + (size_t)tok * HH + n0;
#pragma unroll
                for (int j = 0; j < 2; j++)
#pragma unroll
                    for (int rl = 0; rl < 2; rl++) {
                        int col = wn * 16 + j * 8 + tq * 2 + rl;
                        atomicAdd(ob + col, w * acc[i][j][rh * 2 + rl]);
                    }
            }
        }
    __syncthreads();
}

// ---------------- persistent fused GEMM kernel -----------------------------
__global__ __launch_bounds__(512, 1)
void moe_kernel(const float* __restrict__ hs, const float* __restrict__ W13,
                const float* __restrict__ W2, float* __restrict__ out)
{
    extern __shared__ float sm[];
    int* s_item = (int*)(sm + OFF_TOK + 256);
    int tid = threadIdx.x;
    int ntiles = g_ntiles;
    int ngu = ntiles * 16;
    int total = ntiles * 32;

    for (;;) {
        if (tid == 0) *s_item = atomicAdd(&g_item, 1);
        __syncthreads();
        int item = *s_item;
        __syncthreads();
        if (item >= total) break;
        if (item < ngu) {
            do_gateup(sm, hs, W13, item >> 4, item & 15);
        } else {
            int di = item - ngu;
            do_down(sm, W2, out, di >> 4, di & 15);
        }
        __syncthreads();
    }
}

// ---------------- launch ----------------
extern "C" void kernel_launch(void* const* d_in, const int* in_sizes, int n_in,
                              void* d_out, int out_size)
{
    const float* hs     = (const float*)d_in[0];
    const float* logits = (const float*)d_in[1];
    const float* W13    = (const float*)d_in[2];
    const float* W2     = (const float*)d_in[3];
    float* out = (float*)d_out;

    cudaFuncSetAttribute(moe_kernel, cudaFuncAttributeMaxDynamicSharedMemorySize, SMEM_SZ);

    route_kernel<<<1, TT>>>(logits);
    zero_kernel<<<TT, 256>>>(out);
    moe_kernel<<<NSM, 512, SMEM_SZ>>>(hs, W13, W2, out);
}

// round 17
// speedup vs baseline: 1.5236x; 1.0579x over previous
#include <cuda_runtime.h>
#include <math.h>
#include <stdint.h>

#define TT 1024
#define HH 1024
#define EE 8
#define II 1024
#define NP 2048
#define TM 128
#define NIT 32
#define MAX_TILES 24
#define NSM 148

// word (uint32) SMEM layout
#define A_P   20                 // words per A row: 16 kpair + 4 pad
#define B_P   132                // words per B k-row: 128 + 4 pad
#define AT_FL (128 * A_P)        // 2560
#define BT_FL (32 * B_P)         // 4224
#define OFF_AH0 0
#define OFF_AL0 (AT_FL)
#define OFF_AH1 (2 * AT_FL)
#define OFF_AL1 (3 * AT_FL)
#define OFF_B0  (4 * AT_FL)
#define OFF_B1  (4 * AT_FL + BT_FL)
#define OFF_TOK (4 * AT_FL + 2 * BT_FL)     // 18688 words
#define SMEM_SZ ((OFF_TOK + 256 + 8) * 4)

// ---------------- scratch ----------------
__device__ int   g_counts[EE];
__device__ int   g_offsets[EE];
__device__ int   g_cursor[EE];
__device__ int   g_list[NP];
__device__ float g_w[NP];
__device__ int   g_tile_e[MAX_TILES];
__device__ int   g_tile_row[MAX_TILES];
__device__ int   g_tile_rows[MAX_TILES];
__device__ int   g_ntiles;
__device__ int   g_item;
__device__ int   g_done[MAX_TILES];
__device__ __align__(16) float g_act[(size_t)NP * II];

// ---------------- helpers ----------------
__device__ __forceinline__ void mma_bf16(float* c, const uint32_t* a, const uint32_t* b){
    asm volatile(
        "mma.sync.aligned.m16n8k16.row.col.f32.bf16.bf16.f32 "
        "{%0,%1,%2,%3}, {%4,%5,%6,%7}, {%8,%9}, {%0,%1,%2,%3};"
        : "+f"(c[0]), "+f"(c[1]), "+f"(c[2]), "+f"(c[3])
        : "r"(a[0]), "r"(a[1]), "r"(a[2]), "r"(a[3]), "r"(b[0]), "r"(b[1]));
}
__device__ __forceinline__ uint32_t prmt(uint32_t a, uint32_t b, uint32_t s){
    uint32_t r;
    asm("prmt.b32 %0, %1, %2, %3;" : "=r"(r) : "r"(a), "r"(b), "r"(s));
    return r;
}
// split two floats -> (hiword = bf16(x0)|bf16(x1)<<16, loword = residuals)
__device__ __forceinline__ void split2(float x0, float x1, uint32_t& hw, uint32_t& lw){
    asm("cvt.rn.bf16x2.f32 %0, %1, %2;" : "=r"(hw) : "f"(x1), "f"(x0));
    float f0 = __uint_as_float(hw << 16);
    float f1 = __uint_as_float(hw & 0xFFFF0000u);
    asm("cvt.rn.bf16x2.f32 %0, %1, %2;" : "=r"(lw) : "f"(x1 - f1), "f"(x0 - f0));
}
// per-element packed (hi | lo<<16) for 2 elements
__device__ __forceinline__ void splitE2(float x0, float x1, uint32_t& w0, uint32_t& w1){
    uint32_t hw, lw;
    split2(x0, x1, hw, lw);
    w0 = prmt(hw, lw, 0x5410u);
    w1 = prmt(hw, lw, 0x7632u);
}
__device__ __forceinline__ float fast_sigmoid(float g){
    float y = -g * 1.4426950408889634f;
    y = fminf(fmaxf(y, -126.f), 126.f);
    float kf = rintf(y);
    float z = (y - kf) * 0.6931471805599453f;
    float p = 1.f + z*(1.f + z*(0.5f + z*(0.16666667f + z*(0.041666668f + z*0.008333334f))));
    float e = p * __int_as_float(((int)kf + 127) << 23);
    float d = 1.f + e;
    float r = __uint_as_float(0x7EF127EAu - __float_as_uint(d));
    r = r*(2.f - d*r); r = r*(2.f - d*r); r = r*(2.f - d*r);
    return r;
}

// ---------------- routing ----------------
__global__ void route_kernel(const float* __restrict__ logits)
{
    int t = threadIdx.x;
    if (t < EE) g_counts[t] = 0;
    if (t < MAX_TILES) g_done[t] = 0;
    if (t == 0) g_item = 0;
    __syncthreads();

    float l[EE];
#pragma unroll
    for (int e = 0; e < EE; e++) l[e] = logits[t * EE + e];

    int i0 = 0;
#pragma unroll
    for (int e = 1; e < EE; e++) if (l[e] > l[i0]) i0 = e;
    int i1 = (i0 == 0) ? 1 : 0;
#pragma unroll
    for (int e = 0; e < EE; e++) if (e != i0 && l[e] > l[i1]) i1 = e;

    float e1 = __expf(l[i1] - l[i0]);
    float inv = 1.0f / (1.0f + e1);
    g_w[t * 2 + 0] = inv;
    g_w[t * 2 + 1] = e1 * inv;

    atomicAdd(&g_counts[i0], 1);
    atomicAdd(&g_counts[i1], 1);
    __syncthreads();

    if (t == 0) {
        int off = 0;
        for (int e = 0; e < EE; e++) { g_offsets[e] = off; g_cursor[e] = off; off += g_counts[e]; }
    }
    __syncthreads();

    int p0 = atomicAdd(&g_cursor[i0], 1);
    g_list[p0] = t * 2 + 0;
    int p1 = atomicAdd(&g_cursor[i1], 1);
    g_list[p1] = t * 2 + 1;
    __syncthreads();

    if (t == 0) {
        int n = 0;
        for (int e = 0; e < EE; e++) {
            int c = g_counts[e], o = g_offsets[e];
            for (int s = 0; s < c; s += TM) {
                g_tile_e[n] = e; g_tile_row[n] = o + s; g_tile_rows[n] = min(TM, c - s); n++;
            }
        }
        g_ntiles = n;
    }
}

__global__ void zero_kernel(float* __restrict__ out)
{
    int idx = blockIdx.x * blockDim.x + threadIdx.x;
    ((float4*)out)[idx] = make_float4(0.f, 0.f, 0.f, 0.f);
}

// ---- tile stores ----
// A: split float4 (4 consecutive k at row m) into Ahi/Alo kpair-word tiles
__device__ __forceinline__ void stsA_split(uint32_t* Ahi, uint32_t* Alo,
                                           int tid, int q, const float4& v){
    int idx = tid + q * 512;
    int m = idx >> 3, c4 = idx & 7;          // kpair base = c4*2
    uint32_t h01, l01, h23, l23;
    split2(v.x, v.y, h01, l01);
    split2(v.z, v.w, h23, l23);
    *(uint2*)(Ahi + m * A_P + c4 * 2) = make_uint2(h01, h23);
    *(uint2*)(Alo + m * A_P + c4 * 2) = make_uint2(l01, l23);
}
// B: per-element packed words, natural [k][n] layout
__device__ __forceinline__ void stsB_split(uint32_t* B, int k, int c0, const float4& v){
    uint32_t w0, w1, w2, w3;
    splitE2(v.x, v.y, w0, w1);
    splitE2(v.z, v.w, w2, w3);
    *(uint4*)(B + k * B_P + c0) = make_uint4(w0, w1, w2, w3);
}

// load A frag pair (hi or lo tile): rows mbase..+15, k16 half h
__device__ __forceinline__ void ldfragA(const uint32_t* At, int mbase, int h,
                                        int r, int kq, uint32_t* a){
    const uint32_t* p = At + (mbase + r) * A_P + h * 8 + kq;
    a[0] = p[0];
    a[1] = p[8 * A_P];
    a[2] = p[4];
    a[3] = p[8 * A_P + 4];
}

// ---- gateup compute: warp 32m x 32n, chunk K=32 -> 48 bf16 mma ----
__device__ __forceinline__ void compute_chunk_gu(const uint32_t* __restrict__ Ahi,
                                                 const uint32_t* __restrict__ Alo,
                                                 const uint32_t* __restrict__ B2,
                                                 int lane, int wm, int wn,
                                                 float acc[2][4][4]){
    int r = lane >> 2, kq = lane & 3;
#pragma unroll
    for (int h = 0; h < 2; h++) {
        uint32_t ah0[4], ah1[4], al0[4], al1[4];
        ldfragA(Ahi, wm * 32,      h, r, kq, ah0);
        ldfragA(Ahi, wm * 32 + 16, h, r, kq, ah1);
        ldfragA(Alo, wm * 32,      h, r, kq, al0);
        ldfragA(Alo, wm * 32 + 16, h, r, kq, al1);
        uint32_t bh[4][2], bl[4][2];
        int kb = h * 16 + 2 * kq;
#pragma unroll
        for (int nf = 0; nf < 4; nf++) {
            const uint32_t* p = B2 + kb * B_P + wn * 32 + nf * 8 + r;
            uint32_t w0 = p[0], w1 = p[B_P], w2 = p[8 * B_P], w3 = p[9 * B_P];
            bh[nf][0] = prmt(w0, w1, 0x5410u); bh[nf][1] = prmt(w2, w3, 0x5410u);
            bl[nf][0] = prmt(w0, w1, 0x7632u); bl[nf][1] = prmt(w2, w3, 0x7632u);
        }
#pragma unroll
        for (int nf = 0; nf < 4; nf++) { mma_bf16(acc[0][nf], ah0, bh[nf]); mma_bf16(acc[1][nf], ah1, bh[nf]); }
#pragma unroll
        for (int nf = 0; nf < 4; nf++) { mma_bf16(acc[0][nf], al0, bh[nf]); mma_bf16(acc[1][nf], al1, bh[nf]); }
#pragma unroll
        for (int nf = 0; nf < 4; nf++) { mma_bf16(acc[0][nf], ah0, bl[nf]); mma_bf16(acc[1][nf], ah1, bl[nf]); }
    }
}
// ---- down compute: warp 32m x 16n -> 24 bf16 mma ----
__device__ __forceinline__ void compute_chunk_dn(const uint32_t* __restrict__ Ahi,
                                                 const uint32_t* __restrict__ Alo,
                                                 const uint32_t* __restrict__ B2,
                                                 int lane, int wm, int wn,
                                                 float acc[2][2][4]){
    int r = lane >> 2, kq = lane & 3;
#pragma unroll
    for (int h = 0; h < 2; h++) {
        uint32_t ah0[4], ah1[4], al0[4], al1[4];
        ldfragA(Ahi, wm * 32,      h, r, kq, ah0);
        ldfragA(Ahi, wm * 32 + 16, h, r, kq, ah1);
        ldfragA(Alo, wm * 32,      h, r, kq, al0);
        ldfragA(Alo, wm * 32 + 16, h, r, kq, al1);
        uint32_t bh[2][2], bl[2][2];
        int kb = h * 16 + 2 * kq;
#pragma unroll
        for (int nf = 0; nf < 2; nf++) {
            const uint32_t* p = B2 + kb * B_P + wn * 16 + nf * 8 + r;
            uint32_t w0 = p[0], w1 = p[B_P], w2 = p[8 * B_P], w3 = p[9 * B_P];
            bh[nf][0] = prmt(w0, w1, 0x5410u); bh[nf][1] = prmt(w2, w3, 0x5410u);
            bl[nf][0] = prmt(w0, w1, 0x7632u); bl[nf][1] = prmt(w2, w3, 0x7632u);
        }
#pragma unroll
        for (int nf = 0; nf < 2; nf++) { mma_bf16(acc[0][nf], ah0, bh[nf]); mma_bf16(acc[1][nf], ah1, bh[nf]); }
#pragma unroll
        for (int nf = 0; nf < 2; nf++) { mma_bf16(acc[0][nf], al0, bh[nf]); mma_bf16(acc[1][nf], al1, bh[nf]); }
#pragma unroll
        for (int nf = 0; nf < 2; nf++) { mma_bf16(acc[0][nf], ah0, bl[nf]); mma_bf16(acc[1][nf], ah1, bl[nf]); }
    }
}

// ---------------- gate-up item: 128 rows x (64 gate | 64 up) ---------------
__device__ void do_gateup(float* smf, const float* __restrict__ hs,
                          const float* __restrict__ W13,
                          int tileid, int colblk)
{
    int e = g_tile_e[tileid], row0 = g_tile_row[tileid], rows = g_tile_rows[tileid];
    int n0 = colblk * 64;

    uint32_t* smu = (uint32_t*)smf;
    uint32_t* Ah[2] = { smu + OFF_AH0, smu + OFF_AH1 };
    uint32_t* Al[2] = { smu + OFF_AL0, smu + OFF_AL1 };
    uint32_t* Bb[2] = { smu + OFF_B0,  smu + OFF_B1  };
    int* toks = (int*)(smu + OFF_TOK);

    int tid = threadIdx.x;
    int lane = tid & 31, wid = tid >> 5, wm = wid & 3, wn = wid >> 2;

    if (tid < 128) toks[tid] = (tid < rows) ? (g_list[row0 + tid] >> 1) : -1;
    __syncthreads();

    const float* wb = W13 + (size_t)e * HH * (2 * II);

    int am  = (tid + 0)   >> 3, ac0 = (tid & 7) * 4;
    int am1 = (tid + 512) >> 3;
    int bk  = (tid + 0)   >> 5, bc0 = (tid & 31) * 4;
    int bk1 = (tid + 512) >> 5;
    int t0 = toks[am], t1 = toks[am1];
    const float* bcol = wb + ((bc0 < 64) ? (n0 + bc0) : (II + n0 + (bc0 - 64)));

    float4 pa[2], pb[2];
#define LDGA(it) { int kk = (it)*32; \
    pa[0] = (t0 >= 0) ? *(const float4*)(hs + (size_t)t0 * HH + kk + ac0) : make_float4(0,0,0,0); \
    pa[1] = (t1 >= 0) ? *(const float4*)(hs + (size_t)t1 * HH + kk + ac0) : make_float4(0,0,0,0); }
#define LDGB(it) { int kk = (it)*32; \
    pb[0] = *(const float4*)(bcol + (size_t)(kk + bk ) * (2*II)); \
    pb[1] = *(const float4*)(bcol + (size_t)(kk + bk1) * (2*II)); }
#define STALL(b) { stsA_split(Ah[b], Al[b], tid, 0, pa[0]); stsA_split(Ah[b], Al[b], tid, 1, pa[1]); \
    stsB_split(Bb[b], bk, bc0, pb[0]); stsB_split(Bb[b], bk1, bc0, pb[1]); }

    float acc[2][4][4] = {};

    LDGA(0); LDGB(0);
    STALL(0);
    LDGA(1); LDGB(1);
    __syncthreads();

    for (int it = 0; it < NIT; it++) {
        int cur = it & 1;
        if (it + 1 < NIT) {
            STALL(1 - cur);
            if (it + 2 < NIT) { LDGA(it + 2); LDGB(it + 2); }
        }
        compute_chunk_gu(Ah[cur], Al[cur], Bb[cur], lane, wm, wn, acc);
        __syncthreads();
    }
#undef LDGA
#undef LDGB
#undef STALL

    // stage accs -> smem [128][132] floats
    int g = lane >> 2, t = lane & 3;
#pragma unroll
    for (int i = 0; i < 2; i++)
#pragma unroll
        for (int j = 0; j < 4; j++)
#pragma unroll
            for (int r = 0; r < 4; r++) {
                int row = wm * 32 + i * 16 + ((r >> 1) << 3) + g;
                int col = wn * 32 + j * 8 + t * 2 + (r & 1);
                smf[row * 132 + col] = acc[i][j][r];
            }
    __syncthreads();

#pragma unroll
    for (int q = 0; q < 4; q++) {
        int idx = tid + q * 512;
        int row = idx >> 4, c4 = (idx & 15) * 4;
        if (row < rows) {
            float4 gv = *(const float4*)(smf + row * 132 + c4);
            float4 uv = *(const float4*)(smf + row * 132 + 64 + c4);
            float4 o;
            o.x = gv.x * fast_sigmoid(gv.x) * uv.x;
            o.y = gv.y * fast_sigmoid(gv.y) * uv.y;
            o.z = gv.z * fast_sigmoid(gv.z) * uv.z;
            o.w = gv.w * fast_sigmoid(gv.w) * uv.w;
            *(float4*)(g_act + (size_t)(row0 + row) * II + n0 + c4) = o;
        }
    }
    __threadfence();
    __syncthreads();
    if (tid == 0) atomicAdd(&g_done[tileid], 1);
}

// ---------------- down item: 128 rows x 64 cols, atomicAdd into out --------
__device__ void do_down(float* smf, const float* __restrict__ W2,
                        float* __restrict__ out, int tileid, int colblk)
{
    int e = g_tile_e[tileid], row0 = g_tile_row[tileid], rows = g_tile_rows[tileid];
    int n0 = colblk * 64;
    int tid = threadIdx.x;

    if (tid == 0) { while (atomicAdd(&g_done[tileid], 0) < 16) { } }
    __syncthreads();
    __threadfence();

    uint32_t* smu = (uint32_t*)smf;
    uint32_t* Ah[2] = { smu + OFF_AH0, smu + OFF_AH1 };
    uint32_t* Al[2] = { smu + OFF_AL0, smu + OFF_AL1 };
    uint32_t* Bb[2] = { smu + OFF_B0,  smu + OFF_B1  };
    int*   toks = (int*)(smu + OFF_TOK);
    float* ws   = (float*)(smu + OFF_TOK + 128);

    int lane = tid & 31, wid = tid >> 5, wm = wid & 3, wn = wid >> 2;

    if (tid < 128) {
        if (tid < rows) {
            int li = g_list[row0 + tid];
            toks[tid] = li >> 1;
            ws[tid] = g_w[li];
        } else { toks[tid] = -1; ws[tid] = 0.f; }
    }
    __syncthreads();

    const float* wb = W2 + (size_t)e * II * HH;

    int am  = (tid + 0)   >> 3, ac0 = (tid & 7) * 4;
    int am1 = (tid + 512) >> 3;
    int bk  = tid >> 4, bc0 = (tid & 15) * 4;
    const float* arow0 = (am  < rows) ? (g_act + (size_t)(row0 + am ) * II + ac0) : 0;
    const float* arow1 = (am1 < rows) ? (g_act + (size_t)(row0 + am1) * II + ac0) : 0;
    const float* bcol  = wb + n0 + bc0;

    float4 pa[2], pb;
#define LDGA(it) { int kk = (it)*32; \
    pa[0] = arow0 ? *(const float4*)(arow0 + kk) : make_float4(0,0,0,0); \
    pa[1] = arow1 ? *(const float4*)(arow1 + kk) : make_float4(0,0,0,0); }
#define LDGB(it) { int kk = (it)*32; \
    pb = *(const float4*)(bcol + (size_t)(kk + bk) * HH); }
#define STALL(b) { stsA_split(Ah[b], Al[b], tid, 0, pa[0]); stsA_split(Ah[b], Al[b], tid, 1, pa[1]); \
    stsB_split(Bb[b], bk, bc0, pb); }

    float acc[2][2][4] = {};

    LDGA(0); LDGB(0);
    STALL(0);
    LDGA(1); LDGB(1);
    __syncthreads();

    for (int it = 0; it < NIT; it++) {
        int cur = it & 1;
        if (it + 1 < NIT) {
            STALL(1 - cur);
            if (it + 2 < NIT) { LDGA(it + 2); LDGB(it + 2); }
        }
        compute_chunk_dn(Ah[cur], Al[cur], Bb[cur], lane, wm, wn, acc);
        __syncthreads();
    }
#undef LDGA
#undef LDGB
#undef STALL

    int gq = lane >> 2, tq = lane & 3;
#pragma unroll
    for (int i = 0; i < 2; i++)
#pragma unroll
        for (int rh = 0; rh < 2; rh++) {
            int row = wm * 32 + i * 16 + rh * 8 + gq;
            if (row < rows) {
                int tok = toks[row];
                float w = ws[row];
                float* ob = out + (size_t)tok * HH + n0;
#pragma unroll
                for (int j = 0; j < 2; j++)
#pragma unroll
                    for (int rl = 0; rl < 2; rl++) {
                        int col = wn * 16 + j * 8 + tq * 2 + rl;
                        atomicAdd(ob + col, w * acc[i][j][rh * 2 + rl]);
                    }
            }
        }
    __syncthreads();
}

// ---------------- persistent fused GEMM kernel -----------------------------
__global__ __launch_bounds__(512, 1)
void moe_kernel(const float* __restrict__ hs, const float* __restrict__ W13,
                const float* __restrict__ W2, float* __restrict__ out)
{
    extern __shared__ float sm[];
    int* s_item = (int*)(((uint32_t*)sm) + OFF_TOK + 256);
    int tid = threadIdx.x;
    int ntiles = g_ntiles;
    int ngu = ntiles * 16;
    int total = ntiles * 32;

    for (;;) {
        if (tid == 0) *s_item = atomicAdd(&g_item, 1);
        __syncthreads();
        int item = *s_item;
        __syncthreads();
        if (item >= total) break;
        if (item < ngu) {
            do_gateup(sm, hs, W13, item >> 4, item & 15);
        } else {
            int di = item - ngu;
            do_down(sm, W2, out, di >> 4, di & 15);
        }
        __syncthreads();
    }
}

// ---------------- launch ----------------
extern "C" void kernel_launch(void* const* d_in, const int* in_sizes, int n_in,
                              void* d_out, int out_size)
{
    const float* hs     = (const float*)d_in[0];
    const float* logits = (const float*)d_in[1];
    const float* W13    = (const float*)d_in[2];
    const float* W2     = (const float*)d_in[3];
    float* out = (float*)d_out;

    cudaFuncSetAttribute(moe_kernel, cudaFuncAttributeMaxDynamicSharedMemorySize, SMEM_SZ);

    route_kernel<<<1, TT>>>(logits);
    zero_kernel<<<TT, 256>>>(out);
    moe_kernel<<<NSM, 512, SMEM_SZ>>>(hs, W13, W2, out);
}